// round 4
// baseline (speedup 1.0000x reference)
#include <cuda_runtime.h>
#include <math.h>
#include <stdint.h>

#define CC 512
#define TT 32
#define HH 8
#define DHD 64
#define MAXN 32768
#define MAXB 32

typedef unsigned long long u64;

// ---------------- scratch (device globals; no allocation allowed) -------------
__device__ float g_k[MAXN * CC];
__device__ float g_v[MAXN * CC];
__device__ float g_qh[TT * CC];
__device__ float g_attn[MAXB * TT * CC];
__device__ float g_h[MAXB * TT * CC];
__device__ float g_hn[MAXB * TT * CC];
__device__ float g_ff1[MAXB * TT * 2 * CC];
__device__ int   g_seg[MAXB + 1];

// ---------------- f32x2 packed math helpers ----------------------------------
__device__ __forceinline__ u64 f2pack(float lo, float hi) {
    u64 d; asm("mov.b64 %0, {%1, %2};" : "=l"(d) : "f"(lo), "f"(hi)); return d;
}
__device__ __forceinline__ void f2unpack(u64 d, float& lo, float& hi) {
    asm("mov.b64 {%0, %1}, %2;" : "=f"(lo), "=f"(hi) : "l"(d));
}
__device__ __forceinline__ void fma2(u64& d, u64 a, u64 b) {
    asm("fma.rn.f32x2 %0, %1, %2, %0;" : "+l"(d) : "l"(a), "l"(b));
}

__device__ __forceinline__ float gelu_exact(float x) {
    return 0.5f * x * (1.0f + erff(x * 0.70710678118654752f));
}

// block reduce for 128 threads (4 warps)
__device__ __forceinline__ float blockReduce128(float v, float* sbuf) {
    int lane = threadIdx.x & 31, w = threadIdx.x >> 5;
    #pragma unroll
    for (int o = 16; o; o >>= 1) v += __shfl_down_sync(0xffffffffu, v, o);
    __syncthreads();
    if (lane == 0) sbuf[w] = v;
    __syncthreads();
    return sbuf[0] + sbuf[1] + sbuf[2] + sbuf[3];
}

// ---------------- segment offsets from sorted batch_idx ----------------------
__global__ void seg_kernel(const int* __restrict__ bidx, int n, int nb) {
    int i = blockIdx.x * blockDim.x + threadIdx.x;
    if (i >= n) return;
    int cur = bidx[i];
    int prev = (i == 0) ? -1 : bidx[i - 1];
    for (int x = prev + 1; x <= cur && x <= MAXB; x++) g_seg[x] = i;
    if (i == n - 1)
        for (int x = cur + 1; x <= nb && x <= MAXB; x++) g_seg[x] = n;
}

// ---------------- query LN + projection (grid = T, 128 threads) --------------
__global__ __launch_bounds__(128) void qproj_kernel(
    const float* __restrict__ query, const float* __restrict__ gq,
    const float* __restrict__ bq, const float* __restrict__ wq,
    const float* __restrict__ bqi)
{
    __shared__ __align__(16) float qn[CC];
    __shared__ float sbuf[4];
    int t = blockIdx.x, tid = threadIdx.x;
    const float* qrow = query + (size_t)t * CC;
    float s = 0.f;
    for (int c = tid; c < CC; c += 128) s += qrow[c];
    float mu = blockReduce128(s, sbuf) * (1.0f / CC);
    float vv = 0.f;
    for (int c = tid; c < CC; c += 128) { float d = qrow[c] - mu; vv += d * d; }
    float var = blockReduce128(vv, sbuf) * (1.0f / CC);
    float inv = rsqrtf(var + 1e-5f);
    for (int c = tid; c < CC; c += 128) qn[c] = (qrow[c] - mu) * inv * gq[c] + bq[c];
    __syncthreads();
    const float scale = 0.125f; // 1/sqrt(DH)
    for (int j = tid; j < CC; j += 128) {
        const float* wr = wq + (size_t)j * CC;
        float acc = 0.f;
        #pragma unroll 4
        for (int c = 0; c < CC; c += 4) {
            float4 a = *(const float4*)&qn[c];
            float4 w = *(const float4*)&wr[c];
            acc += a.x * w.x + a.y * w.y + a.z * w.z + a.w * w.w;
        }
        g_qh[t * CC + j] = (acc + bqi[j]) * scale;
    }
}

// ---------------- layernorm over rows (grid = rows, 128 threads) -------------
__global__ __launch_bounds__(128) void ln_kernel(
    const float* __restrict__ X, const float* __restrict__ g,
    const float* __restrict__ b, float* __restrict__ Y)
{
    __shared__ float sbuf[4];
    int r = blockIdx.x, tid = threadIdx.x;
    const float* x = X + (size_t)r * CC;
    float s = 0.f;
    for (int c = tid; c < CC; c += 128) s += x[c];
    float mu = blockReduce128(s, sbuf) * (1.0f / CC);
    float vv = 0.f;
    for (int c = tid; c < CC; c += 128) { float d = x[c] - mu; vv += d * d; }
    float var = blockReduce128(vv, sbuf) * (1.0f / CC);
    float inv = rsqrtf(var + 1e-5f);
    float* y = Y + (size_t)r * CC;
    for (int c = tid; c < CC; c += 128) y[c] = (x[c] - mu) * inv * g[c] + b[c];
}

// ---------------- GEMM tiling constants --------------------------------------
#define BM 128
#define BN 64
#define BK 16
#define ASTR (BM + 4)
#define BSTR (BN + 4)

// ---------------- fused K+V projection GEMM ----------------------------------
// Ck[m,j] = sum_k A[m,k]*Wk[j,k] + bk[j];  Cv likewise. One A smem tile feeds
// both weight tiles: halves feat gmem traffic and CTA count vs two launches.
__global__ __launch_bounds__(256) void gemm_kv(
    const float* __restrict__ A,
    const float* __restrict__ Wk, const float* __restrict__ Wv,
    const float* __restrict__ biask, const float* __restrict__ biasv,
    float* __restrict__ Ck, float* __restrict__ Cv, int K)
{
    __shared__ __align__(16) float As[BK * ASTR];
    __shared__ __align__(16) float Bks[BK * BSTR];
    __shared__ __align__(16) float Bvs[BK * BSTR];
    int tid = threadIdx.x;
    int bm = blockIdx.y * BM;
    int bn = blockIdx.x * BN;

    int tx = tid & 15, ty = tid >> 4;
    int m0 = ty * 8, n0 = tx * 4;

    int ar0 = tid >> 2;
    int ak0 = (tid & 3) * 4;
    int br  = tid >> 2;
    int bk0 = (tid & 3) * 4;

    u64 ak[16], av[16];
    #pragma unroll
    for (int i = 0; i < 16; i++) { ak[i] = 0ULL; av[i] = 0ULL; }

    const float* Ar0 = A + (size_t)(bm + ar0) * K;
    const float* Ar1 = A + (size_t)(bm + ar0 + 64) * K;
    const float* Wkr = Wk + (size_t)(bn + br) * K;
    const float* Wvr = Wv + (size_t)(bn + br) * K;

    float4 pa0 = *(const float4*)(Ar0 + ak0);
    float4 pa1 = *(const float4*)(Ar1 + ak0);
    float4 pbk = *(const float4*)(Wkr + bk0);
    float4 pbv = *(const float4*)(Wvr + bk0);

    int nIter = K / BK;
    for (int it = 0; it < nIter; it++) {
        As[(ak0 + 0) * ASTR + ar0] = pa0.x;
        As[(ak0 + 1) * ASTR + ar0] = pa0.y;
        As[(ak0 + 2) * ASTR + ar0] = pa0.z;
        As[(ak0 + 3) * ASTR + ar0] = pa0.w;
        As[(ak0 + 0) * ASTR + ar0 + 64] = pa1.x;
        As[(ak0 + 1) * ASTR + ar0 + 64] = pa1.y;
        As[(ak0 + 2) * ASTR + ar0 + 64] = pa1.z;
        As[(ak0 + 3) * ASTR + ar0 + 64] = pa1.w;
        Bks[(bk0 + 0) * BSTR + br] = pbk.x;
        Bks[(bk0 + 1) * BSTR + br] = pbk.y;
        Bks[(bk0 + 2) * BSTR + br] = pbk.z;
        Bks[(bk0 + 3) * BSTR + br] = pbk.w;
        Bvs[(bk0 + 0) * BSTR + br] = pbv.x;
        Bvs[(bk0 + 1) * BSTR + br] = pbv.y;
        Bvs[(bk0 + 2) * BSTR + br] = pbv.z;
        Bvs[(bk0 + 3) * BSTR + br] = pbv.w;
        __syncthreads();
        if (it + 1 < nIter) {
            int ko = (it + 1) * BK;
            pa0 = *(const float4*)(Ar0 + ko + ak0);
            pa1 = *(const float4*)(Ar1 + ko + ak0);
            pbk = *(const float4*)(Wkr + ko + bk0);
            pbv = *(const float4*)(Wvr + ko + bk0);
        }
        #pragma unroll
        for (int kk = 0; kk < BK; kk++) {
            const u64* ap = (const u64*)&As[kk * ASTR + m0];
            u64 a0 = ap[0], a1 = ap[1], a2 = ap[2], a3 = ap[3];
            float4 bk4 = *(const float4*)&Bks[kk * BSTR + n0];
            float4 bv4 = *(const float4*)&Bvs[kk * BSTR + n0];
            u64 k0 = f2pack(bk4.x, bk4.x);
            u64 k1 = f2pack(bk4.y, bk4.y);
            u64 k2 = f2pack(bk4.z, bk4.z);
            u64 k3 = f2pack(bk4.w, bk4.w);
            fma2(ak[0],  a0, k0); fma2(ak[1],  a1, k0);
            fma2(ak[2],  a2, k0); fma2(ak[3],  a3, k0);
            fma2(ak[4],  a0, k1); fma2(ak[5],  a1, k1);
            fma2(ak[6],  a2, k1); fma2(ak[7],  a3, k1);
            fma2(ak[8],  a0, k2); fma2(ak[9],  a1, k2);
            fma2(ak[10], a2, k2); fma2(ak[11], a3, k2);
            fma2(ak[12], a0, k3); fma2(ak[13], a1, k3);
            fma2(ak[14], a2, k3); fma2(ak[15], a3, k3);
            u64 v0 = f2pack(bv4.x, bv4.x);
            u64 v1 = f2pack(bv4.y, bv4.y);
            u64 v2 = f2pack(bv4.z, bv4.z);
            u64 v3 = f2pack(bv4.w, bv4.w);
            fma2(av[0],  a0, v0); fma2(av[1],  a1, v0);
            fma2(av[2],  a2, v0); fma2(av[3],  a3, v0);
            fma2(av[4],  a0, v1); fma2(av[5],  a1, v1);
            fma2(av[6],  a2, v1); fma2(av[7],  a3, v1);
            fma2(av[8],  a0, v2); fma2(av[9],  a1, v2);
            fma2(av[10], a2, v2); fma2(av[11], a3, v2);
            fma2(av[12], a0, v3); fma2(av[13], a1, v3);
            fma2(av[14], a2, v3); fma2(av[15], a3, v3);
        }
        __syncthreads();
    }

    // vectorized epilogue: assemble float4 per row, one STG.128 per row
    float4 bk4 = *(const float4*)&biask[bn + n0];
    float4 bv4 = *(const float4*)&biasv[bn + n0];
    #pragma unroll
    for (int mp = 0; mp < 4; mp++) {
        int row = bm + m0 + 2 * mp;
        float l0, h0, l1, h1, l2, h2, l3, h3;
        f2unpack(ak[0 * 4 + mp], l0, h0);
        f2unpack(ak[1 * 4 + mp], l1, h1);
        f2unpack(ak[2 * 4 + mp], l2, h2);
        f2unpack(ak[3 * 4 + mp], l3, h3);
        *(float4*)&Ck[(size_t)row * CC + bn + n0] =
            make_float4(l0 + bk4.x, l1 + bk4.y, l2 + bk4.z, l3 + bk4.w);
        *(float4*)&Ck[(size_t)(row + 1) * CC + bn + n0] =
            make_float4(h0 + bk4.x, h1 + bk4.y, h2 + bk4.z, h3 + bk4.w);
        f2unpack(av[0 * 4 + mp], l0, h0);
        f2unpack(av[1 * 4 + mp], l1, h1);
        f2unpack(av[2 * 4 + mp], l2, h2);
        f2unpack(av[3 * 4 + mp], l3, h3);
        *(float4*)&Cv[(size_t)row * CC + bn + n0] =
            make_float4(l0 + bv4.x, l1 + bv4.y, l2 + bv4.z, l3 + bv4.w);
        *(float4*)&Cv[(size_t)(row + 1) * CC + bn + n0] =
            make_float4(h0 + bv4.x, h1 + bv4.y, h2 + bv4.z, h3 + bv4.w);
    }
}

// ---------------- generic TN SGEMM:  C[m,j] = epi(sum_k A[m,k]*W[j,k]) -------
// act: 0=none, 1=exact gelu. res: optional residual, row indexed modulo
// res_mod, stride Nout.
__global__ __launch_bounds__(256) void gemm_tn(
    const float* __restrict__ A, const float* __restrict__ W,
    const float* __restrict__ bias, const float* __restrict__ res,
    float* __restrict__ Cout, int M, int Nout, int K, int res_mod, int act)
{
    __shared__ __align__(16) float As[BK * ASTR];
    __shared__ __align__(16) float Bs[BK * BSTR];
    int tid = threadIdx.x;
    int bm = blockIdx.y * BM;
    int bn = blockIdx.x * BN;

    int tx = tid & 15, ty = tid >> 4;
    int m0 = ty * 8, n0 = tx * 4;

    int ar0 = tid >> 2;
    int ak0 = (tid & 3) * 4;
    int br  = tid >> 2;
    int bk0 = (tid & 3) * 4;

    u64 acc[16];
    #pragma unroll
    for (int i = 0; i < 16; i++) acc[i] = 0ULL;

    const float* Ar0 = A + (size_t)(bm + ar0) * K;
    const float* Ar1 = A + (size_t)(bm + ar0 + 64) * K;
    const float* Wr  = W + (size_t)(bn + br) * K;

    float4 pa0 = *(const float4*)(Ar0 + ak0);
    float4 pa1 = *(const float4*)(Ar1 + ak0);
    float4 pb  = *(const float4*)(Wr + bk0);

    int nIter = K / BK;
    for (int it = 0; it < nIter; it++) {
        As[(ak0 + 0) * ASTR + ar0] = pa0.x;
        As[(ak0 + 1) * ASTR + ar0] = pa0.y;
        As[(ak0 + 2) * ASTR + ar0] = pa0.z;
        As[(ak0 + 3) * ASTR + ar0] = pa0.w;
        As[(ak0 + 0) * ASTR + ar0 + 64] = pa1.x;
        As[(ak0 + 1) * ASTR + ar0 + 64] = pa1.y;
        As[(ak0 + 2) * ASTR + ar0 + 64] = pa1.z;
        As[(ak0 + 3) * ASTR + ar0 + 64] = pa1.w;
        Bs[(bk0 + 0) * BSTR + br] = pb.x;
        Bs[(bk0 + 1) * BSTR + br] = pb.y;
        Bs[(bk0 + 2) * BSTR + br] = pb.z;
        Bs[(bk0 + 3) * BSTR + br] = pb.w;
        __syncthreads();
        if (it + 1 < nIter) {
            int ko = (it + 1) * BK;
            pa0 = *(const float4*)(Ar0 + ko + ak0);
            pa1 = *(const float4*)(Ar1 + ko + ak0);
            pb  = *(const float4*)(Wr + ko + bk0);
        }
        #pragma unroll
        for (int kk = 0; kk < BK; kk++) {
            const u64* ap = (const u64*)&As[kk * ASTR + m0];
            u64 a0 = ap[0], a1 = ap[1], a2 = ap[2], a3 = ap[3];
            float4 bv = *(const float4*)&Bs[kk * BSTR + n0];
            u64 b0 = f2pack(bv.x, bv.x);
            u64 b1 = f2pack(bv.y, bv.y);
            u64 b2 = f2pack(bv.z, bv.z);
            u64 b3 = f2pack(bv.w, bv.w);
            fma2(acc[0],  a0, b0); fma2(acc[1],  a1, b0);
            fma2(acc[2],  a2, b0); fma2(acc[3],  a3, b0);
            fma2(acc[4],  a0, b1); fma2(acc[5],  a1, b1);
            fma2(acc[6],  a2, b1); fma2(acc[7],  a3, b1);
            fma2(acc[8],  a0, b2); fma2(acc[9],  a1, b2);
            fma2(acc[10], a2, b2); fma2(acc[11], a3, b2);
            fma2(acc[12], a0, b3); fma2(acc[13], a1, b3);
            fma2(acc[14], a2, b3); fma2(acc[15], a3, b3);
        }
        __syncthreads();
    }

    // vectorized epilogue
    float4 bias4 = bias ? *(const float4*)&bias[bn + n0]
                        : make_float4(0.f, 0.f, 0.f, 0.f);
    #pragma unroll
    for (int mp = 0; mp < 4; mp++) {
        int row = bm + m0 + 2 * mp;
        float l0, h0, l1, h1, l2, h2, l3, h3;
        f2unpack(acc[0 * 4 + mp], l0, h0);
        f2unpack(acc[1 * 4 + mp], l1, h1);
        f2unpack(acc[2 * 4 + mp], l2, h2);
        f2unpack(acc[3 * 4 + mp], l3, h3);
        float4 r0 = make_float4(l0 + bias4.x, l1 + bias4.y, l2 + bias4.z, l3 + bias4.w);
        float4 r1 = make_float4(h0 + bias4.x, h1 + bias4.y, h2 + bias4.z, h3 + bias4.w);
        if (act == 1) {
            r0.x = gelu_exact(r0.x); r0.y = gelu_exact(r0.y);
            r0.z = gelu_exact(r0.z); r0.w = gelu_exact(r0.w);
            r1.x = gelu_exact(r1.x); r1.y = gelu_exact(r1.y);
            r1.z = gelu_exact(r1.z); r1.w = gelu_exact(r1.w);
        }
        if (res) {
            float4 q0 = *(const float4*)&res[(size_t)(row % res_mod) * Nout + bn + n0];
            float4 q1 = *(const float4*)&res[(size_t)((row + 1) % res_mod) * Nout + bn + n0];
            r0.x += q0.x; r0.y += q0.y; r0.z += q0.z; r0.w += q0.w;
            r1.x += q1.x; r1.y += q1.y; r1.z += q1.z; r1.w += q1.w;
        }
        *(float4*)&Cout[(size_t)row * Nout + bn + n0] = r0;
        *(float4*)&Cout[(size_t)(row + 1) * Nout + bn + n0] = r1;
    }
}

// ---------------- segmented flash attention (one CTA per (b,h)) --------------
#define KT 64
#define QSTR 68
#define KSTR 68
#define PSTR 68
// floats: qs 32*68=2176 | ks 64*68=4352 | vs 64*64=4096 | ps 32*68=2176 | ml 64
#define OFF_KS 2176
#define OFF_VS 6528
#define OFF_PS 10624
#define OFF_ML 12800
#define ATTN_SMEM_FLOATS 12864
#define ATTN_SMEM_BYTES (ATTN_SMEM_FLOATS * 4)

__global__ __launch_bounds__(256) void attn_kernel() {
    extern __shared__ __align__(16) float sm[];
    float* qs = sm;
    float* ks = sm + OFF_KS;
    float* vs = sm + OFF_VS;
    float* ps = sm + OFF_PS;
    float* mrow = sm + OFF_ML;
    float* lrow = mrow + TT;

    int b = blockIdx.x >> 3, h = blockIdx.x & 7;
    int s0 = g_seg[b], s1 = g_seg[b + 1];
    int tid = threadIdx.x;

    for (int i = tid; i < TT * DHD; i += 256) {
        int t = i >> 6, d = i & 63;
        qs[t * QSTR + d] = g_qh[t * CC + h * DHD + d];
    }
    if (tid < TT) { mrow[tid] = -1e30f; lrow[tid] = 0.f; }

    float acc[8];
    #pragma unroll
    for (int i = 0; i < 8; i++) acc[i] = 0.f;
    int tq = tid >> 3;            // t owned for p*v accumulation (0..31)
    int dg = (tid & 7) * 8;       // d-chunk owned (0..56)
    float mold = -1e30f;
    __syncthreads();

    for (int base = s0; base < s1; base += KT) {
        int lim = min(KT, s1 - base);
        // load K (transposed) and V tiles, zero-fill tail rows
        for (int i = tid; i < KT * (DHD / 4); i += 256) {
            int r = i >> 4, c4 = (i & 15) << 2;
            float4 kv = make_float4(0.f, 0.f, 0.f, 0.f);
            float4 vv = make_float4(0.f, 0.f, 0.f, 0.f);
            if (r < lim) {
                size_t off = (size_t)(base + r) * CC + h * DHD + c4;
                kv = *(const float4*)&g_k[off];
                vv = *(const float4*)&g_v[off];
            }
            ks[(c4 + 0) * KSTR + r] = kv.x;
            ks[(c4 + 1) * KSTR + r] = kv.y;
            ks[(c4 + 2) * KSTR + r] = kv.z;
            ks[(c4 + 3) * KSTR + r] = kv.w;
            *(float4*)&vs[r * DHD + c4] = vv;
        }
        __syncthreads();
        // scores s[t][j0..j0+8] (qh already carries 1/sqrt(DH))
        {
            float sa[8];
            #pragma unroll
            for (int i = 0; i < 8; i++) sa[i] = 0.f;
            const float* qp = &qs[tq * QSTR];
            #pragma unroll 8
            for (int d = 0; d < DHD; d++) {
                float qv = qp[d];
                const float* kr = &ks[d * KSTR + dg];
                float4 k0 = *(const float4*)kr;
                float4 k1 = *(const float4*)(kr + 4);
                sa[0] += qv * k0.x; sa[1] += qv * k0.y;
                sa[2] += qv * k0.z; sa[3] += qv * k0.w;
                sa[4] += qv * k1.x; sa[5] += qv * k1.y;
                sa[6] += qv * k1.z; sa[7] += qv * k1.w;
            }
            *(float4*)&ps[tq * PSTR + dg]     = make_float4(sa[0], sa[1], sa[2], sa[3]);
            *(float4*)&ps[tq * PSTR + dg + 4] = make_float4(sa[4], sa[5], sa[6], sa[7]);
        }
        __syncthreads();
        // per-row online softmax update (32 leader threads)
        if (tid < TT) {
            int t = tid;
            float mo = mrow[t];
            float mx = mo;
            for (int j = 0; j < lim; j++) mx = fmaxf(mx, ps[t * PSTR + j]);
            float l = lrow[t] * __expf(mo - mx);
            for (int j = 0; j < KT; j++) {
                float p = (j < lim) ? __expf(ps[t * PSTR + j] - mx) : 0.f;
                ps[t * PSTR + j] = p;
                l += p;
            }
            mrow[t] = mx; lrow[t] = l;
        }
        __syncthreads();
        // rescale + accumulate p*V
        {
            float c = __expf(mold - mrow[tq]);
            mold = mrow[tq];
            #pragma unroll
            for (int i = 0; i < 8; i++) acc[i] *= c;
            const float* pp = &ps[tq * PSTR];
            for (int j = 0; j < KT; j++) {
                float p = pp[j];
                const float* vr = &vs[j * DHD + dg];
                float4 v0 = *(const float4*)vr;
                float4 v1 = *(const float4*)(vr + 4);
                acc[0] += p * v0.x; acc[1] += p * v0.y;
                acc[2] += p * v0.z; acc[3] += p * v0.w;
                acc[4] += p * v1.x; acc[5] += p * v1.y;
                acc[6] += p * v1.z; acc[7] += p * v1.w;
            }
        }
        __syncthreads();
    }
    float l = lrow[tq];
    float linv = (l > 0.f) ? 1.f / l : 0.f;
    size_t off = (size_t)(b * TT + tq) * CC + h * DHD + dg;
    *(float4*)&g_attn[off]     = make_float4(acc[0] * linv, acc[1] * linv, acc[2] * linv, acc[3] * linv);
    *(float4*)&g_attn[off + 4] = make_float4(acc[4] * linv, acc[5] * linv, acc[6] * linv, acc[7] * linv);
}

// ---------------- launch ------------------------------------------------------
extern "C" void kernel_launch(void* const* d_in, const int* in_sizes, int n_in,
                              void* d_out, int out_size) {
    const float* feat = (const float*)d_in[0];
    const int* bidx   = (const int*)d_in[1];
    // batch_size may or may not be materialized as an input tensor
    int p = (n_in >= 20) ? 3 : 2;
    const float* query = (const float*)d_in[p + 0];
    const float* gq    = (const float*)d_in[p + 1];
    const float* bq    = (const float*)d_in[p + 2];
    const float* wq    = (const float*)d_in[p + 3];
    const float* wk    = (const float*)d_in[p + 4];
    const float* wv    = (const float*)d_in[p + 5];
    const float* bqi   = (const float*)d_in[p + 6];
    const float* bki   = (const float*)d_in[p + 7];
    const float* bvi   = (const float*)d_in[p + 8];
    const float* wo    = (const float*)d_in[p + 9];
    const float* bo    = (const float*)d_in[p + 10];
    const float* gff   = (const float*)d_in[p + 11];
    const float* bff   = (const float*)d_in[p + 12];
    const float* w1    = (const float*)d_in[p + 13];
    const float* b1    = (const float*)d_in[p + 14];
    const float* w2    = (const float*)d_in[p + 15];
    const float* b2    = (const float*)d_in[p + 16];

    int N = in_sizes[1];
    int B = out_size / (TT * CC);
    float* out = (float*)d_out;

    float *pk, *pv, *pattn, *ph, *phn, *pff1;
    cudaGetSymbolAddress((void**)&pk, g_k);
    cudaGetSymbolAddress((void**)&pv, g_v);
    cudaGetSymbolAddress((void**)&pattn, g_attn);
    cudaGetSymbolAddress((void**)&ph, g_h);
    cudaGetSymbolAddress((void**)&phn, g_hn);
    cudaGetSymbolAddress((void**)&pff1, g_ff1);

    seg_kernel<<<(N + 255) / 256, 256>>>(bidx, N, B);
    qproj_kernel<<<TT, 128>>>(query, gq, bq, wq, bqi);

    // fused K & V projections
    dim3 gkv(CC / BN, N / BM);
    gemm_kv<<<gkv, 256>>>(feat, wk, wv, bki, bvi, pk, pv, CC);

    cudaFuncSetAttribute(attn_kernel, cudaFuncAttributeMaxDynamicSharedMemorySize,
                         ATTN_SMEM_BYTES);
    attn_kernel<<<B * HH, 256, ATTN_SMEM_BYTES>>>();

    int M = B * TT;
    dim3 g1(CC / BN, M / BM);
    // h = attn @ wo^T + bo + query(broadcast over batch)
    gemm_tn<<<g1, 256>>>(pattn, wo, bo, query, ph, M, CC, CC, TT, 0);
    ln_kernel<<<M, 128>>>(ph, gff, bff, phn);
    dim3 g3(2 * CC / BN, M / BM);
    // ff1 = gelu(hn @ w1^T + b1)
    gemm_tn<<<g3, 256>>>(phn, w1, b1, nullptr, pff1, M, 2 * CC, CC, 1 << 30, 1);
    // out = h + ff1 @ w2^T + b2
    gemm_tn<<<g1, 256>>>(pff1, w2, b2, ph, out, M, CC, 2 * CC, 1 << 30, 0);
}

// round 7
// speedup vs baseline: 1.4156x; 1.4156x over previous
#include <cuda_runtime.h>
#include <math.h>
#include <stdint.h>

#define CC 512
#define TT 32
#define HH 8
#define DHD 64
#define MAXN 32768
#define MAXB 32
#define NCH 16

typedef unsigned long long u64;

// ---------------- scratch (device globals; no allocation allowed) -------------
__device__ float g_k[MAXN * CC];
__device__ float g_v[MAXN * CC];
__device__ float g_qh[TT * CC];
__device__ float g_attn[MAXB * TT * CC];
__device__ float g_h[MAXB * TT * CC];
__device__ float g_hn[MAXB * TT * CC];
__device__ float g_ff1[MAXB * TT * 2 * CC];
__device__ int   g_seg[MAXB + 1];
// attention split-K partials
__device__ float g_pm[MAXB * HH * NCH * TT];
__device__ float g_pl[MAXB * HH * NCH * TT];
__device__ float g_pacc[MAXB * HH * NCH * TT * DHD];

// ---------------- f32x2 packed math helpers ----------------------------------
__device__ __forceinline__ u64 f2pack(float lo, float hi) {
    u64 d; asm("mov.b64 %0, {%1, %2};" : "=l"(d) : "f"(lo), "f"(hi)); return d;
}
__device__ __forceinline__ void f2unpack(u64 d, float& lo, float& hi) {
    asm("mov.b64 {%0, %1}, %2;" : "=f"(lo), "=f"(hi) : "l"(d));
}
__device__ __forceinline__ void fma2(u64& d, u64 a, u64 b) {
    asm("fma.rn.f32x2 %0, %1, %2, %0;" : "+l"(d) : "l"(a), "l"(b));
}

// ---------------- tf32 mma helpers --------------------------------------------
__device__ __forceinline__ uint32_t f2tf(float x) {
    uint32_t r; asm("cvt.rna.tf32.f32 %0, %1;" : "=r"(r) : "f"(x)); return r;
}
__device__ __forceinline__ void mma_tf32(float* c, const uint32_t* a, const uint32_t* b) {
    asm("mma.sync.aligned.m16n8k8.row.col.f32.tf32.tf32.f32 "
        "{%0,%1,%2,%3},{%4,%5,%6,%7},{%8,%9},{%0,%1,%2,%3};"
        : "+f"(c[0]), "+f"(c[1]), "+f"(c[2]), "+f"(c[3])
        : "r"(a[0]), "r"(a[1]), "r"(a[2]), "r"(a[3]), "r"(b[0]), "r"(b[1]));
}

__device__ __forceinline__ float gelu_exact(float x) {
    return 0.5f * x * (1.0f + erff(x * 0.70710678118654752f));
}

// block reduce for 128 threads (4 warps)
__device__ __forceinline__ float blockReduce128(float v, float* sbuf) {
    int lane = threadIdx.x & 31, w = threadIdx.x >> 5;
    #pragma unroll
    for (int o = 16; o; o >>= 1) v += __shfl_down_sync(0xffffffffu, v, o);
    __syncthreads();
    if (lane == 0) sbuf[w] = v;
    __syncthreads();
    return sbuf[0] + sbuf[1] + sbuf[2] + sbuf[3];
}

// ---------------- segment offsets from sorted batch_idx ----------------------
__global__ void seg_kernel(const int* __restrict__ bidx, int n, int nb) {
    int i = blockIdx.x * blockDim.x + threadIdx.x;
    if (i >= n) return;
    int cur = bidx[i];
    int prev = (i == 0) ? -1 : bidx[i - 1];
    for (int x = prev + 1; x <= cur && x <= MAXB; x++) g_seg[x] = i;
    if (i == n - 1)
        for (int x = cur + 1; x <= nb && x <= MAXB; x++) g_seg[x] = n;
}

// ---------------- query LN + projection (grid = T, 128 threads) --------------
__global__ __launch_bounds__(128) void qproj_kernel(
    const float* __restrict__ query, const float* __restrict__ gq,
    const float* __restrict__ bq, const float* __restrict__ wq,
    const float* __restrict__ bqi)
{
    __shared__ __align__(16) float qn[CC];
    __shared__ float sbuf[4];
    int t = blockIdx.x, tid = threadIdx.x;
    const float* qrow = query + (size_t)t * CC;
    float s = 0.f;
    for (int c = tid; c < CC; c += 128) s += qrow[c];
    float mu = blockReduce128(s, sbuf) * (1.0f / CC);
    float vv = 0.f;
    for (int c = tid; c < CC; c += 128) { float d = qrow[c] - mu; vv += d * d; }
    float var = blockReduce128(vv, sbuf) * (1.0f / CC);
    float inv = rsqrtf(var + 1e-5f);
    for (int c = tid; c < CC; c += 128) qn[c] = (qrow[c] - mu) * inv * gq[c] + bq[c];
    __syncthreads();
    const float scale = 0.125f; // 1/sqrt(DH)
    for (int j = tid; j < CC; j += 128) {
        const float* wr = wq + (size_t)j * CC;
        float acc = 0.f;
        #pragma unroll 4
        for (int c = 0; c < CC; c += 4) {
            float4 a = *(const float4*)&qn[c];
            float4 w = *(const float4*)&wr[c];
            acc += a.x * w.x + a.y * w.y + a.z * w.z + a.w * w.w;
        }
        g_qh[t * CC + j] = (acc + bqi[j]) * scale;
    }
}

// ---------------- layernorm over rows (grid = rows, 128 threads) -------------
__global__ __launch_bounds__(128) void ln_kernel(
    const float* __restrict__ X, const float* __restrict__ g,
    const float* __restrict__ b, float* __restrict__ Y)
{
    __shared__ float sbuf[4];
    int r = blockIdx.x, tid = threadIdx.x;
    const float* x = X + (size_t)r * CC;
    float s = 0.f;
    for (int c = tid; c < CC; c += 128) s += x[c];
    float mu = blockReduce128(s, sbuf) * (1.0f / CC);
    float vv = 0.f;
    for (int c = tid; c < CC; c += 128) { float d = x[c] - mu; vv += d * d; }
    float var = blockReduce128(vv, sbuf) * (1.0f / CC);
    float inv = rsqrtf(var + 1e-5f);
    float* y = Y + (size_t)r * CC;
    for (int c = tid; c < CC; c += 128) y[c] = (x[c] - mu) * inv * g[c] + b[c];
}

// ---------------- GEMM tiling constants --------------------------------------
#define BM 128
#define BN 64
#define BK 16
#define ASTR (BM + 4)
#define BSTR (BN + 4)

// ---------------- fused K+V projection via tf32 mma.sync ----------------------
// C[m,j] = sum_k A[m,k]*W[j,k] + bias[j] for both Wk and Wv from one A tile.
// 8 warps in 4x2 (m x n) grid, warp tile 32x32, m16n8k8 tf32 fragments,
// fp32 accumulation. Inputs rounded to tf32 once at smem-stage time.
__global__ __launch_bounds__(256) void gemm_kv(
    const float* __restrict__ A,
    const float* __restrict__ Wk, const float* __restrict__ Wv,
    const float* __restrict__ biask, const float* __restrict__ biasv,
    float* __restrict__ Ck, float* __restrict__ Cv, int K)
{
    __shared__ __align__(16) uint32_t As[BK * ASTR];
    __shared__ __align__(16) uint32_t Bks[BK * BSTR];
    __shared__ __align__(16) uint32_t Bvs[BK * BSTR];
    int tid = threadIdx.x;
    int bm = blockIdx.y * BM;
    int bn = blockIdx.x * BN;

    int warp = tid >> 5, lane = tid & 31;
    int wm = warp >> 1, wn = warp & 1;       // warp tile origin (wm*32, wn*32)
    int grp = lane >> 2, qd = lane & 3;

    int ar0 = tid >> 2;            // A stage rows ar0, ar0+64
    int ak0 = (tid & 3) * 4;
    int br  = tid >> 2;
    int bk0 = (tid & 3) * 4;

    float accK[2][4][4], accV[2][4][4];
    #pragma unroll
    for (int mi = 0; mi < 2; mi++)
        #pragma unroll
        for (int ni = 0; ni < 4; ni++)
            #pragma unroll
            for (int r = 0; r < 4; r++) { accK[mi][ni][r] = 0.f; accV[mi][ni][r] = 0.f; }

    const float* Ar0 = A + (size_t)(bm + ar0) * K;
    const float* Ar1 = A + (size_t)(bm + ar0 + 64) * K;
    const float* Wkr = Wk + (size_t)(bn + br) * K;
    const float* Wvr = Wv + (size_t)(bn + br) * K;

    float4 pa0 = *(const float4*)(Ar0 + ak0);
    float4 pa1 = *(const float4*)(Ar1 + ak0);
    float4 pbk = *(const float4*)(Wkr + bk0);
    float4 pbv = *(const float4*)(Wvr + bk0);

    int nIter = K / BK;
    for (int it = 0; it < nIter; it++) {
        As[(ak0 + 0) * ASTR + ar0] = f2tf(pa0.x);
        As[(ak0 + 1) * ASTR + ar0] = f2tf(pa0.y);
        As[(ak0 + 2) * ASTR + ar0] = f2tf(pa0.z);
        As[(ak0 + 3) * ASTR + ar0] = f2tf(pa0.w);
        As[(ak0 + 0) * ASTR + ar0 + 64] = f2tf(pa1.x);
        As[(ak0 + 1) * ASTR + ar0 + 64] = f2tf(pa1.y);
        As[(ak0 + 2) * ASTR + ar0 + 64] = f2tf(pa1.z);
        As[(ak0 + 3) * ASTR + ar0 + 64] = f2tf(pa1.w);
        Bks[(bk0 + 0) * BSTR + br] = f2tf(pbk.x);
        Bks[(bk0 + 1) * BSTR + br] = f2tf(pbk.y);
        Bks[(bk0 + 2) * BSTR + br] = f2tf(pbk.z);
        Bks[(bk0 + 3) * BSTR + br] = f2tf(pbk.w);
        Bvs[(bk0 + 0) * BSTR + br] = f2tf(pbv.x);
        Bvs[(bk0 + 1) * BSTR + br] = f2tf(pbv.y);
        Bvs[(bk0 + 2) * BSTR + br] = f2tf(pbv.z);
        Bvs[(bk0 + 3) * BSTR + br] = f2tf(pbv.w);
        __syncthreads();
        if (it + 1 < nIter) {
            int ko = (it + 1) * BK;
            pa0 = *(const float4*)(Ar0 + ko + ak0);
            pa1 = *(const float4*)(Ar1 + ko + ak0);
            pbk = *(const float4*)(Wkr + ko + bk0);
            pbv = *(const float4*)(Wvr + ko + bk0);
        }
        #pragma unroll
        for (int k0 = 0; k0 < BK; k0 += 8) {
            uint32_t aF[2][4];
            #pragma unroll
            for (int mi = 0; mi < 2; mi++) {
                int m = wm * 32 + mi * 16 + grp;
                aF[mi][0] = As[(k0 + qd) * ASTR + m];
                aF[mi][1] = As[(k0 + qd) * ASTR + m + 8];
                aF[mi][2] = As[(k0 + qd + 4) * ASTR + m];
                aF[mi][3] = As[(k0 + qd + 4) * ASTR + m + 8];
            }
            uint32_t bK[4][2], bV[4][2];
            #pragma unroll
            for (int ni = 0; ni < 4; ni++) {
                int n = wn * 32 + ni * 8 + grp;
                bK[ni][0] = Bks[(k0 + qd) * BSTR + n];
                bK[ni][1] = Bks[(k0 + qd + 4) * BSTR + n];
                bV[ni][0] = Bvs[(k0 + qd) * BSTR + n];
                bV[ni][1] = Bvs[(k0 + qd + 4) * BSTR + n];
            }
            #pragma unroll
            for (int mi = 0; mi < 2; mi++)
                #pragma unroll
                for (int ni = 0; ni < 4; ni++) {
                    mma_tf32(accK[mi][ni], aF[mi], bK[ni]);
                    mma_tf32(accV[mi][ni], aF[mi], bV[ni]);
                }
        }
        __syncthreads();
    }

    // epilogue: c0,c1 = (row, col..col+1), c2,c3 = (row+8, col..col+1)
    #pragma unroll
    for (int mi = 0; mi < 2; mi++) {
        int row = bm + wm * 32 + mi * 16 + grp;
        #pragma unroll
        for (int ni = 0; ni < 4; ni++) {
            int col = bn + wn * 32 + ni * 8 + qd * 2;
            float bk0v = biask[col], bk1v = biask[col + 1];
            float bv0v = biasv[col], bv1v = biasv[col + 1];
            *(float2*)&Ck[(size_t)row * CC + col] =
                make_float2(accK[mi][ni][0] + bk0v, accK[mi][ni][1] + bk1v);
            *(float2*)&Ck[(size_t)(row + 8) * CC + col] =
                make_float2(accK[mi][ni][2] + bk0v, accK[mi][ni][3] + bk1v);
            *(float2*)&Cv[(size_t)row * CC + col] =
                make_float2(accV[mi][ni][0] + bv0v, accV[mi][ni][1] + bv1v);
            *(float2*)&Cv[(size_t)(row + 8) * CC + col] =
                make_float2(accV[mi][ni][2] + bv0v, accV[mi][ni][3] + bv1v);
        }
    }
}

// ---------------- generic TN SGEMM (fp32 f32x2; small M) ----------------------
__global__ __launch_bounds__(256) void gemm_tn(
    const float* __restrict__ A, const float* __restrict__ W,
    const float* __restrict__ bias, const float* __restrict__ res,
    float* __restrict__ Cout, int M, int Nout, int K, int res_mod, int act)
{
    __shared__ __align__(16) float As[BK * ASTR];
    __shared__ __align__(16) float Bs[BK * BSTR];
    int tid = threadIdx.x;
    int bm = blockIdx.y * BM;
    int bn = blockIdx.x * BN;

    int tx = tid & 15, ty = tid >> 4;
    int m0 = ty * 8, n0 = tx * 4;

    int ar0 = tid >> 2;
    int ak0 = (tid & 3) * 4;
    int br  = tid >> 2;
    int bk0 = (tid & 3) * 4;

    u64 acc[16];
    #pragma unroll
    for (int i = 0; i < 16; i++) acc[i] = 0ULL;

    const float* Ar0 = A + (size_t)(bm + ar0) * K;
    const float* Ar1 = A + (size_t)(bm + ar0 + 64) * K;
    const float* Wr  = W + (size_t)(bn + br) * K;

    float4 pa0 = *(const float4*)(Ar0 + ak0);
    float4 pa1 = *(const float4*)(Ar1 + ak0);
    float4 pb  = *(const float4*)(Wr + bk0);

    int nIter = K / BK;
    for (int it = 0; it < nIter; it++) {
        As[(ak0 + 0) * ASTR + ar0] = pa0.x;
        As[(ak0 + 1) * ASTR + ar0] = pa0.y;
        As[(ak0 + 2) * ASTR + ar0] = pa0.z;
        As[(ak0 + 3) * ASTR + ar0] = pa0.w;
        As[(ak0 + 0) * ASTR + ar0 + 64] = pa1.x;
        As[(ak0 + 1) * ASTR + ar0 + 64] = pa1.y;
        As[(ak0 + 2) * ASTR + ar0 + 64] = pa1.z;
        As[(ak0 + 3) * ASTR + ar0 + 64] = pa1.w;
        Bs[(bk0 + 0) * BSTR + br] = pb.x;
        Bs[(bk0 + 1) * BSTR + br] = pb.y;
        Bs[(bk0 + 2) * BSTR + br] = pb.z;
        Bs[(bk0 + 3) * BSTR + br] = pb.w;
        __syncthreads();
        if (it + 1 < nIter) {
            int ko = (it + 1) * BK;
            pa0 = *(const float4*)(Ar0 + ko + ak0);
            pa1 = *(const float4*)(Ar1 + ko + ak0);
            pb  = *(const float4*)(Wr + ko + bk0);
        }
        #pragma unroll
        for (int kk = 0; kk < BK; kk++) {
            const u64* ap = (const u64*)&As[kk * ASTR + m0];
            u64 a0 = ap[0], a1 = ap[1], a2 = ap[2], a3 = ap[3];
            float4 bv = *(const float4*)&Bs[kk * BSTR + n0];
            u64 b0 = f2pack(bv.x, bv.x);
            u64 b1 = f2pack(bv.y, bv.y);
            u64 b2 = f2pack(bv.z, bv.z);
            u64 b3 = f2pack(bv.w, bv.w);
            fma2(acc[0],  a0, b0); fma2(acc[1],  a1, b0);
            fma2(acc[2],  a2, b0); fma2(acc[3],  a3, b0);
            fma2(acc[4],  a0, b1); fma2(acc[5],  a1, b1);
            fma2(acc[6],  a2, b1); fma2(acc[7],  a3, b1);
            fma2(acc[8],  a0, b2); fma2(acc[9],  a1, b2);
            fma2(acc[10], a2, b2); fma2(acc[11], a3, b2);
            fma2(acc[12], a0, b3); fma2(acc[13], a1, b3);
            fma2(acc[14], a2, b3); fma2(acc[15], a3, b3);
        }
        __syncthreads();
    }

    float4 bias4 = bias ? *(const float4*)&bias[bn + n0]
                        : make_float4(0.f, 0.f, 0.f, 0.f);
    #pragma unroll
    for (int mp = 0; mp < 4; mp++) {
        int row = bm + m0 + 2 * mp;
        float l0, h0, l1, h1, l2, h2, l3, h3;
        f2unpack(acc[0 * 4 + mp], l0, h0);
        f2unpack(acc[1 * 4 + mp], l1, h1);
        f2unpack(acc[2 * 4 + mp], l2, h2);
        f2unpack(acc[3 * 4 + mp], l3, h3);
        float4 r0 = make_float4(l0 + bias4.x, l1 + bias4.y, l2 + bias4.z, l3 + bias4.w);
        float4 r1 = make_float4(h0 + bias4.x, h1 + bias4.y, h2 + bias4.z, h3 + bias4.w);
        if (act == 1) {
            r0.x = gelu_exact(r0.x); r0.y = gelu_exact(r0.y);
            r0.z = gelu_exact(r0.z); r0.w = gelu_exact(r0.w);
            r1.x = gelu_exact(r1.x); r1.y = gelu_exact(r1.y);
            r1.z = gelu_exact(r1.z); r1.w = gelu_exact(r1.w);
        }
        if (res) {
            float4 q0 = *(const float4*)&res[(size_t)(row % res_mod) * Nout + bn + n0];
            float4 q1 = *(const float4*)&res[(size_t)((row + 1) % res_mod) * Nout + bn + n0];
            r0.x += q0.x; r0.y += q0.y; r0.z += q0.z; r0.w += q0.w;
            r1.x += q1.x; r1.y += q1.y; r1.z += q1.z; r1.w += q1.w;
        }
        *(float4*)&Cout[(size_t)row * Nout + bn + n0] = r0;
        *(float4*)&Cout[(size_t)(row + 1) * Nout + bn + n0] = r1;
    }
}

// ---------------- split-K segmented flash attention, pass 1 -------------------
#define KT 64
#define QSTR 68
#define KSTR 68
#define PSTR 68
#define OFF_KS 2176
#define OFF_VS 6528
#define OFF_PS 10624
#define ATTN_SMEM_FLOATS 12800
#define ATTN_SMEM_BYTES (ATTN_SMEM_FLOATS * 4)

__global__ __launch_bounds__(256) void attn_part() {
    extern __shared__ __align__(16) float sm[];
    float* qs = sm;
    float* ks = sm + OFF_KS;
    float* vs = sm + OFF_VS;
    float* ps = sm + OFF_PS;

    int bh = blockIdx.x;
    int ci = blockIdx.y;
    int b = bh >> 3, h = bh & 7;
    int s0 = g_seg[b], s1 = g_seg[b + 1];
    int seglen = s1 - s0;
    int L = (seglen + NCH - 1) / NCH;
    int start = s0 + ci * L;
    int end = min(start + L, s1);

    int tid = threadIdx.x;
    int t = tid >> 3;
    int g = tid & 7;
    int dg = g * 8;

    size_t pbase = ((size_t)bh * NCH + ci) * TT;
    if (start >= end) {
        if (g == 0) { g_pm[pbase + t] = -1e30f; g_pl[pbase + t] = 0.f; }
        return;
    }

    for (int i = tid; i < TT * DHD; i += 256) {
        int tt = i >> 6, d = i & 63;
        qs[tt * QSTR + d] = g_qh[tt * CC + h * DHD + d];
    }

    float m = -1e30f, l = 0.f;
    float acc[8];
    #pragma unroll
    for (int i = 0; i < 8; i++) acc[i] = 0.f;
    __syncthreads();

    for (int base = start; base < end; base += KT) {
        int lim = min(KT, end - base);
        for (int i = tid; i < KT * (DHD / 4); i += 256) {
            int r = i >> 4, c4 = (i & 15) << 2;
            float4 kv = make_float4(0.f, 0.f, 0.f, 0.f);
            float4 vv = make_float4(0.f, 0.f, 0.f, 0.f);
            if (r < lim) {
                size_t off = (size_t)(base + r) * CC + h * DHD + c4;
                kv = *(const float4*)&g_k[off];
                vv = *(const float4*)&g_v[off];
            }
            ks[(c4 + 0) * KSTR + r] = kv.x;
            ks[(c4 + 1) * KSTR + r] = kv.y;
            ks[(c4 + 2) * KSTR + r] = kv.z;
            ks[(c4 + 3) * KSTR + r] = kv.w;
            *(float4*)&vs[r * DHD + c4] = vv;
        }
        __syncthreads();

        float sa[8];
        #pragma unroll
        for (int i = 0; i < 8; i++) sa[i] = 0.f;
        {
            const float* qp = &qs[t * QSTR];
            #pragma unroll 8
            for (int d = 0; d < DHD; d++) {
                float qv = qp[d];
                const float* kr = &ks[d * KSTR + dg];
                float4 k0 = *(const float4*)kr;
                float4 k1 = *(const float4*)(kr + 4);
                sa[0] += qv * k0.x; sa[1] += qv * k0.y;
                sa[2] += qv * k0.z; sa[3] += qv * k0.w;
                sa[4] += qv * k1.x; sa[5] += qv * k1.y;
                sa[6] += qv * k1.z; sa[7] += qv * k1.w;
            }
        }
        #pragma unroll
        for (int i = 0; i < 8; i++)
            if (dg + i >= lim) sa[i] = -1e30f;

        float mloc = sa[0];
        #pragma unroll
        for (int i = 1; i < 8; i++) mloc = fmaxf(mloc, sa[i]);
        #pragma unroll
        for (int o = 1; o < 8; o <<= 1)
            mloc = fmaxf(mloc, __shfl_xor_sync(0xffffffffu, mloc, o));
        float mnew = fmaxf(m, mloc);
        float corr = __expf(m - mnew);
        float p[8];
        float ls = 0.f;
        #pragma unroll
        for (int i = 0; i < 8; i++) { p[i] = __expf(sa[i] - mnew); ls += p[i]; }
        #pragma unroll
        for (int o = 1; o < 8; o <<= 1)
            ls += __shfl_xor_sync(0xffffffffu, ls, o);
        l = l * corr + ls;
        m = mnew;
        #pragma unroll
        for (int i = 0; i < 8; i++) acc[i] *= corr;

        *(float4*)&ps[t * PSTR + dg]     = make_float4(p[0], p[1], p[2], p[3]);
        *(float4*)&ps[t * PSTR + dg + 4] = make_float4(p[4], p[5], p[6], p[7]);
        __syncwarp();

        {
            const float* pp = &ps[t * PSTR];
            for (int j = 0; j < KT; j++) {
                float pj = pp[j];
                const float* vr = &vs[j * DHD + dg];
                float4 v0 = *(const float4*)vr;
                float4 v1 = *(const float4*)(vr + 4);
                acc[0] += pj * v0.x; acc[1] += pj * v0.y;
                acc[2] += pj * v0.z; acc[3] += pj * v0.w;
                acc[4] += pj * v1.x; acc[5] += pj * v1.y;
                acc[6] += pj * v1.z; acc[7] += pj * v1.w;
            }
        }
        __syncthreads();
    }

    if (g == 0) { g_pm[pbase + t] = m; g_pl[pbase + t] = l; }
    size_t aoff = (pbase + t) * DHD + dg;
    *(float4*)&g_pacc[aoff]     = make_float4(acc[0], acc[1], acc[2], acc[3]);
    *(float4*)&g_pacc[aoff + 4] = make_float4(acc[4], acc[5], acc[6], acc[7]);
}

// ---------------- attention pass 2: merge partials ----------------------------
__global__ __launch_bounds__(256) void attn_merge() {
    int bh = blockIdx.x;
    int b = bh >> 3, h = bh & 7;
    int tid = threadIdx.x;
    int t = tid >> 3, dg = (tid & 7) * 8;

    size_t base0 = (size_t)bh * NCH * TT;
    float M = -1e30f;
    #pragma unroll
    for (int ci = 0; ci < NCH; ci++)
        M = fmaxf(M, g_pm[base0 + ci * TT + t]);

    float denom = 0.f;
    float acc[8];
    #pragma unroll
    for (int i = 0; i < 8; i++) acc[i] = 0.f;
    for (int ci = 0; ci < NCH; ci++) {
        float lci = g_pl[base0 + ci * TT + t];
        if (lci > 0.f) {
            float w = __expf(g_pm[base0 + ci * TT + t] - M);
            denom += w * lci;
            size_t aoff = (base0 + ci * TT + t) * DHD + dg;
            float4 a0 = *(const float4*)&g_pacc[aoff];
            float4 a1 = *(const float4*)&g_pacc[aoff + 4];
            acc[0] += w * a0.x; acc[1] += w * a0.y;
            acc[2] += w * a0.z; acc[3] += w * a0.w;
            acc[4] += w * a1.x; acc[5] += w * a1.y;
            acc[6] += w * a1.z; acc[7] += w * a1.w;
        }
    }
    float inv = (denom > 0.f) ? 1.f / denom : 0.f;
    size_t off = (size_t)(b * TT + t) * CC + h * DHD + dg;
    *(float4*)&g_attn[off]     = make_float4(acc[0] * inv, acc[1] * inv, acc[2] * inv, acc[3] * inv);
    *(float4*)&g_attn[off + 4] = make_float4(acc[4] * inv, acc[5] * inv, acc[6] * inv, acc[7] * inv);
}

// ---------------- launch ------------------------------------------------------
extern "C" void kernel_launch(void* const* d_in, const int* in_sizes, int n_in,
                              void* d_out, int out_size) {
    const float* feat = (const float*)d_in[0];
    const int* bidx   = (const int*)d_in[1];
    int p = (n_in >= 20) ? 3 : 2;
    const float* query = (const float*)d_in[p + 0];
    const float* gq    = (const float*)d_in[p + 1];
    const float* bq    = (const float*)d_in[p + 2];
    const float* wq    = (const float*)d_in[p + 3];
    const float* wk    = (const float*)d_in[p + 4];
    const float* wv    = (const float*)d_in[p + 5];
    const float* bqi   = (const float*)d_in[p + 6];
    const float* bki   = (const float*)d_in[p + 7];
    const float* bvi   = (const float*)d_in[p + 8];
    const float* wo    = (const float*)d_in[p + 9];
    const float* bo    = (const float*)d_in[p + 10];
    const float* gff   = (const float*)d_in[p + 11];
    const float* bff   = (const float*)d_in[p + 12];
    const float* w1    = (const float*)d_in[p + 13];
    const float* b1    = (const float*)d_in[p + 14];
    const float* w2    = (const float*)d_in[p + 15];
    const float* b2    = (const float*)d_in[p + 16];

    int N = in_sizes[1];
    int B = out_size / (TT * CC);
    float* out = (float*)d_out;

    float *pk, *pv, *pattn, *ph, *phn, *pff1;
    cudaGetSymbolAddress((void**)&pk, g_k);
    cudaGetSymbolAddress((void**)&pv, g_v);
    cudaGetSymbolAddress((void**)&pattn, g_attn);
    cudaGetSymbolAddress((void**)&ph, g_h);
    cudaGetSymbolAddress((void**)&phn, g_hn);
    cudaGetSymbolAddress((void**)&pff1, g_ff1);

    seg_kernel<<<(N + 255) / 256, 256>>>(bidx, N, B);
    qproj_kernel<<<TT, 128>>>(query, gq, bq, wq, bqi);

    // fused K & V projections (tf32 tensor-core path)
    dim3 gkv(CC / BN, N / BM);
    gemm_kv<<<gkv, 256>>>(feat, wk, wv, bki, bvi, pk, pv, CC);

    // split-K attention: pass 1 partials, pass 2 merge
    cudaFuncSetAttribute(attn_part, cudaFuncAttributeMaxDynamicSharedMemorySize,
                         ATTN_SMEM_BYTES);
    dim3 ga(B * HH, NCH);
    attn_part<<<ga, 256, ATTN_SMEM_BYTES>>>();
    attn_merge<<<B * HH, 256>>>();

    int M = B * TT;
    dim3 g1(CC / BN, M / BM);
    gemm_tn<<<g1, 256>>>(pattn, wo, bo, query, ph, M, CC, CC, TT, 0);
    ln_kernel<<<M, 128>>>(ph, gff, bff, phn);
    dim3 g3(2 * CC / BN, M / BM);
    gemm_tn<<<g3, 256>>>(phn, w1, b1, nullptr, pff1, M, 2 * CC, CC, 1 << 30, 1);
    gemm_tn<<<g1, 256>>>(pff1, w2, b2, ph, out, M, CC, 2 * CC, 1 << 30, 0);
}